// round 4
// baseline (speedup 1.0000x reference)
#include <cuda_runtime.h>
#include <math.h>

// Problem constants
#define Bn 16
#define Tn 28
#define Hn 32
#define Wn 32
#define HW 1024
#define Fh 64
#define NIMG (Bn * Tn)   // 448
#define D2 32            // both directions fused: 32 "images" of hidden state

// ---------------- device scratch (no allocations allowed) ----------------
__device__ float g_xgf[(size_t)NIMG * HW * 192];  // xg forward direction
__device__ float g_xgb[(size_t)NIMG * HW * 192];  // xg backward direction
__device__ float g_x0 [(size_t)NIMG * HW * 128];  // layer-0 bidir output
__device__ float g_y1 [(size_t)NIMG * HW * 128];  // layer-1 bidir output
__device__ float g_ha [(size_t)D2 * HW * Fh];     // hidden state ping
__device__ float g_hb [(size_t)D2 * HW * Fh];     // hidden state pong
__device__ float g_zr [(size_t)D2 * HW * 128];    // sigmoided z (0-63) and r (64-127)

// ---------------- packed f32x2 helpers (FFMA2 path) ----------------
__device__ __forceinline__ unsigned long long pack2(float v) {
    unsigned long long r;
    asm("mov.b64 %0, {%1, %1};" : "=l"(r) : "f"(v));
    return r;
}
__device__ __forceinline__ void ffma2(unsigned long long& d, unsigned long long a,
                                      unsigned long long b) {
    asm("fma.rn.f32x2 %0, %1, %2, %0;" : "+l"(d) : "l"(a), "l"(b));
}
__device__ __forceinline__ void unpack2(unsigned long long a, float& lo, float& hi) {
    asm("mov.b64 {%0, %1}, %2;" : "=f"(lo), "=f"(hi) : "l"(a));
}

// Inner accumulate: one cin chunk of 16, 32 couts/thread.
// s_in: [ci][rows*18] with plane stride PS ; ib = py*18+px
// s_w : [k][ci][32] cout-contiguous (warp-broadcast float4 loads)
template<int PS>
__device__ __forceinline__ void accum16(const float* __restrict__ s_in,
                                        const float* __restrict__ s_w,
                                        int ib, unsigned long long acc[16]) {
#pragma unroll
    for (int k = 0; k < 9; k++) {
        const int off = (k / 3) * 18 + (k % 3);
#pragma unroll
        for (int ci = 0; ci < 16; ci++) {
            unsigned long long v2 = pack2(s_in[ci * PS + ib + off]);
            const float* wr = &s_w[(k * 16 + ci) * 32];
#pragma unroll
            for (int j = 0; j < 8; j++) {
                ulonglong2 wv = *(const ulonglong2*)(wr + j * 4);
                ffma2(acc[2 * j],     v2, wv.x);
                ffma2(acc[2 * j + 1], v2, wv.y);
            }
        }
    }
}

// ---------------- generic 3x3 SAME conv, NHWC fp32 (big launches: xg) -------
// grid: (4 tiles of 16x16, n_img, cout_groups_of_32), block 256
__global__ void __launch_bounds__(256)
conv3x3(const float* __restrict__ in, int cin,
        const float* __restrict__ w, int wcs, int wco,
        const float* __restrict__ bias,
        float* __restrict__ out, int ocs, int oco)
{
    __shared__ __align__(16) float s_in[16 * 325];
    __shared__ __align__(16) float s_w[9 * 16 * 32];

    const int tid = threadIdx.x;
    const int px = tid & 15, py = tid >> 4;
    const int tx0 = (blockIdx.x & 1) * 16, ty0 = (blockIdx.x >> 1) * 16;
    const int img = blockIdx.y;
    const int cg  = blockIdx.z;

    const float* inb = in + (size_t)img * HW * cin;

    unsigned long long acc[16];
#pragma unroll
    for (int i = 0; i < 16; i++) acc[i] = 0ull;

    const int nchunk = (cin + 15) >> 4;
    for (int ch = 0; ch < nchunk; ch++) {
        const int cc = ch * 16;
        __syncthreads();
        for (int idx = tid; idx < 18 * 18 * 16; idx += 256) {
            const int ci  = idx & 15;
            const int pix = idx >> 4;
            const int rx = pix % 18, ry = pix / 18;
            const int gy = ty0 + ry - 1, gx = tx0 + rx - 1;
            const int c = cc + ci;
            float v = 0.f;
            if (gy >= 0 && gy < Hn && gx >= 0 && gx < Wn && c < cin)
                v = inb[((size_t)gy * Wn + gx) * cin + c];
            s_in[ci * 325 + ry * 18 + rx] = v;
        }
        for (int idx = tid; idx < 9 * 16 * 32; idx += 256) {
            const int co = idx & 31;
            const int ci = (idx >> 5) & 15;
            const int k  = idx >> 9;
            const int c  = cc + ci;
            float v = 0.f;
            if (c < cin)
                v = w[((size_t)k * cin + c) * wcs + wco + cg * 32 + co];
            s_w[idx] = v;
        }
        __syncthreads();
        accum16<325>(s_in, s_w, py * 18 + px, acc);
    }

    float res[32];
#pragma unroll
    for (int i = 0; i < 16; i++) unpack2(acc[i], res[2 * i], res[2 * i + 1]);
    if (bias) {
#pragma unroll
        for (int i = 0; i < 32; i++) res[i] += bias[cg * 32 + i];
    }
    const size_t obase =
        ((size_t)img * HW + (size_t)(ty0 + py) * Wn + (tx0 + px)) * ocs + oco + cg * 32;
#pragma unroll
    for (int i = 0; i < 8; i++) {
        float4 v = make_float4(res[4 * i], res[4 * i + 1], res[4 * i + 2], res[4 * i + 3]);
        *(float4*)(out + obase + 4 * i) = v;
    }
}

// ---------------- scan step kernel 1: zr = sigmoid(xg + conv(h, wh_zr)) -----
// grid: (8 tiles of 16x8, 32 imgs (dir*16+b), 4 cgroups), block 128
__global__ void __launch_bounds__(128)
gru_k1(const float* __restrict__ h,
       const float* __restrict__ whf, const float* __restrict__ whb,
       const float* __restrict__ xgf, const float* __restrict__ xgb,
       float* __restrict__ zr, int s)
{
    __shared__ __align__(16) float s_in[16 * 181];
    __shared__ __align__(16) float s_w[9 * 16 * 32];

    const int tid = threadIdx.x;
    const int px = tid & 15, py = tid >> 4;          // py 0..7
    const int tx0 = (blockIdx.x & 1) * 16, ty0 = (blockIdx.x >> 1) * 8;
    const int img = blockIdx.y;
    const int cg  = blockIdx.z;
    const int dir = img >> 4;

    const float* hb = h + (size_t)img * HW * Fh;
    const float* wh = dir ? whb : whf;

    unsigned long long acc[16];
#pragma unroll
    for (int i = 0; i < 16; i++) acc[i] = 0ull;

    for (int ch = 0; ch < 4; ch++) {
        const int cc = ch * 16;
        __syncthreads();
        for (int idx = tid; idx < 10 * 18 * 16; idx += 128) {
            const int ci  = idx & 15;
            const int pix = idx >> 4;
            const int rx = pix % 18, ry = pix / 18;
            const int gy = ty0 + ry - 1, gx = tx0 + rx - 1;
            float v = 0.f;
            if (gy >= 0 && gy < Hn && gx >= 0 && gx < Wn)
                v = hb[((size_t)gy * Wn + gx) * Fh + cc + ci];
            s_in[ci * 181 + ry * 18 + rx] = v;
        }
        for (int idx = tid; idx < 9 * 16 * 32; idx += 128) {
            const int co = idx & 31;
            const int ci = (idx >> 5) & 15;
            const int k  = idx >> 9;
            s_w[idx] = wh[((size_t)k * Fh + cc + ci) * 192 + cg * 32 + co];
        }
        __syncthreads();
        accum16<181>(s_in, s_w, py * 18 + px, acc);
    }

    float res[32];
#pragma unroll
    for (int i = 0; i < 16; i++) unpack2(acc[i], res[2 * i], res[2 * i + 1]);

    const int b = img & 15;
    const int t = dir ? (Tn - 1 - s) : s;
    const int gpx = (ty0 + py) * Wn + tx0 + px;
    const float* xp = (dir ? xgb : xgf) + ((size_t)(b * Tn + t) * HW + gpx) * 192 + cg * 32;
    float* zp = zr + ((size_t)img * HW + gpx) * 128 + cg * 32;
#pragma unroll
    for (int i = 0; i < 32; i++) {
        zp[i] = 1.f / (1.f + expf(-(xp[i] + res[i])));
    }
}

// ---------------- scan step kernel 2: full GRU update -----------------------
// acc = conv(r*h, wh_h) formed via r*h in the loader; epilogue does
// hn = z*h + (1-z)*tanh(xg_h + acc), writes hn and y.
// grid: (8 tiles, 32 imgs, 2 cgroups), block 128
__global__ void __launch_bounds__(128)
gru_k2(const float* __restrict__ h,
       const float* __restrict__ whf, const float* __restrict__ whb,
       const float* __restrict__ xgf, const float* __restrict__ xgb,
       const float* __restrict__ zr, float* __restrict__ hn,
       float* __restrict__ y, int s)
{
    __shared__ __align__(16) float s_in[16 * 181];
    __shared__ __align__(16) float s_w[9 * 16 * 32];

    const int tid = threadIdx.x;
    const int px = tid & 15, py = tid >> 4;
    const int tx0 = (blockIdx.x & 1) * 16, ty0 = (blockIdx.x >> 1) * 8;
    const int img = blockIdx.y;
    const int cg  = blockIdx.z;      // 0..1
    const int dir = img >> 4;

    const float* hbase  = h  + (size_t)img * HW * Fh;
    const float* zrbase = zr + (size_t)img * HW * 128;
    const float* wh = dir ? whb : whf;

    unsigned long long acc[16];
#pragma unroll
    for (int i = 0; i < 16; i++) acc[i] = 0ull;

    for (int ch = 0; ch < 4; ch++) {
        const int cc = ch * 16;
        __syncthreads();
        for (int idx = tid; idx < 10 * 18 * 16; idx += 128) {
            const int ci  = idx & 15;
            const int pix = idx >> 4;
            const int rx = pix % 18, ry = pix / 18;
            const int gy = ty0 + ry - 1, gx = tx0 + rx - 1;
            float v = 0.f;
            if (gy >= 0 && gy < Hn && gx >= 0 && gx < Wn) {
                const size_t p = (size_t)gy * Wn + gx;
                v = zrbase[p * 128 + 64 + cc + ci] * hbase[p * Fh + cc + ci];
            }
            s_in[ci * 181 + ry * 18 + rx] = v;
        }
        for (int idx = tid; idx < 9 * 16 * 32; idx += 128) {
            const int co = idx & 31;
            const int ci = (idx >> 5) & 15;
            const int k  = idx >> 9;
            s_w[idx] = wh[((size_t)k * Fh + cc + ci) * 192 + 128 + cg * 32 + co];
        }
        __syncthreads();
        accum16<181>(s_in, s_w, py * 18 + px, acc);
    }

    float res[32];
#pragma unroll
    for (int i = 0; i < 16; i++) unpack2(acc[i], res[2 * i], res[2 * i + 1]);

    const int b = img & 15;
    const int t = dir ? (Tn - 1 - s) : s;
    const int gpx = (ty0 + py) * Wn + tx0 + px;
    const int c0 = cg * 32;
    const size_t frame = (size_t)(b * Tn + t) * HW + gpx;
    const float* xp = (dir ? xgb : xgf) + frame * 192 + 128 + c0;
    const float* zp = zrbase + (size_t)gpx * 128 + c0;
    const float* hp = hbase + (size_t)gpx * Fh + c0;
    float* hnp = hn + ((size_t)img * HW + gpx) * Fh + c0;
    float* yp  = y + frame * 128 + dir * 64 + c0;
#pragma unroll
    for (int i = 0; i < 32; i++) {
        const float hh = tanhf(xp[i] + res[i]);
        const float zz = zp[i];
        const float v  = zz * hp[i] + (1.f - zz) * hh;
        hnp[i] = v;
        yp[i]  = v;
    }
}

// ---------------- fused head: 3x3 conv (256->32) + 1x1 (32->1) + ReLU -------
__global__ void __launch_bounds__(256)
final_conv(const float* __restrict__ x0, const float* __restrict__ y1,
           const float* __restrict__ wc, const float* __restrict__ bc,
           const float* __restrict__ wo, const float* __restrict__ bo,
           float* __restrict__ out)
{
    __shared__ __align__(16) float s_in[16 * 325];
    __shared__ __align__(16) float s_w[9 * 16 * 32];

    const int tid = threadIdx.x;
    const int px = tid & 15, py = tid >> 4;
    const int tx0 = (blockIdx.x & 1) * 16, ty0 = (blockIdx.x >> 1) * 16;
    const int img = blockIdx.y;

    const float* x0b = x0 + (size_t)img * HW * 128;
    const float* y1b = y1 + (size_t)img * HW * 128;

    unsigned long long acc[16];
#pragma unroll
    for (int i = 0; i < 16; i++) acc[i] = 0ull;

    for (int ch = 0; ch < 16; ch++) {
        const int cc = ch * 16;
        __syncthreads();
        for (int idx = tid; idx < 18 * 18 * 16; idx += 256) {
            const int ci  = idx & 15;
            const int pix = idx >> 4;
            const int rx = pix % 18, ry = pix / 18;
            const int gy = ty0 + ry - 1, gx = tx0 + rx - 1;
            float v = 0.f;
            if (gy >= 0 && gy < Hn && gx >= 0 && gx < Wn) {
                const int c = cc + ci;
                const size_t pbase = ((size_t)gy * Wn + gx) * 128;
                v = (c < 128) ? (x0b[pbase + c] + y1b[pbase + c]) : x0b[pbase + c - 128];
            }
            s_in[ci * 325 + ry * 18 + rx] = v;
        }
        for (int idx = tid; idx < 9 * 16 * 32; idx += 256) {
            const int co = idx & 31;
            const int ci = (idx >> 5) & 15;
            const int k  = idx >> 9;
            s_w[idx] = wc[((size_t)k * 256 + cc + ci) * 32 + co];
        }
        __syncthreads();
        accum16<325>(s_in, s_w, py * 18 + px, acc);
    }

    float res[32];
#pragma unroll
    for (int i = 0; i < 16; i++) unpack2(acc[i], res[2 * i], res[2 * i + 1]);

    float o = bo[0];
#pragma unroll
    for (int i = 0; i < 32; i++) o += (res[i] + bc[i]) * wo[i];
    o = fmaxf(o, 0.f);
    out[(size_t)img * HW + (size_t)(ty0 + py) * Wn + (tx0 + px)] = o;
}

// ---------------- host orchestration ----------------
static void run_layer(const float* in, int cin,
                      const float* wxf, const float* bf, const float* whf,
                      const float* wxb, const float* bb, const float* whb,
                      float* xgf, float* xgb, float* ha, float* hbuf, float* zr,
                      float* yout)
{
    // xg for both directions (big parallel convs)
    conv3x3<<<dim3(4, NIMG, 6), 256>>>(in, cin, wxf, 192, 0, bf, xgf, 192, 0);
    conv3x3<<<dim3(4, NIMG, 6), 256>>>(in, cin, wxb, 192, 0, bb, xgb, 192, 0);
    cudaMemsetAsync(ha, 0, (size_t)D2 * HW * Fh * sizeof(float));
    float* hc = ha;
    float* hx = hbuf;
    for (int s = 0; s < Tn; s++) {
        gru_k1<<<dim3(8, D2, 4), 128>>>(hc, whf, whb, xgf, xgb, zr, s);
        gru_k2<<<dim3(8, D2, 2), 128>>>(hc, whf, whb, xgf, xgb, zr, hx, yout, s);
        float* tmp = hc; hc = hx; hx = tmp;
    }
}

extern "C" void kernel_launch(void* const* d_in, const int* in_sizes, int n_in,
                              void* d_out, int out_size)
{
    (void)in_sizes; (void)n_in; (void)out_size;
    const float* x       = (const float*)d_in[0];
    const float* wx_f0   = (const float*)d_in[1];
    const float* wh_f0   = (const float*)d_in[2];
    const float* b_f0    = (const float*)d_in[3];
    const float* wx_b0   = (const float*)d_in[4];
    const float* wh_b0   = (const float*)d_in[5];
    const float* b_b0    = (const float*)d_in[6];
    const float* wx_f1   = (const float*)d_in[7];
    const float* wh_f1   = (const float*)d_in[8];
    const float* b_f1    = (const float*)d_in[9];
    const float* wx_b1   = (const float*)d_in[10];
    const float* wh_b1   = (const float*)d_in[11];
    const float* b_b1    = (const float*)d_in[12];
    const float* w_conv1 = (const float*)d_in[13];
    const float* b_conv1 = (const float*)d_in[14];
    const float* w_out   = (const float*)d_in[15];
    const float* b_out   = (const float*)d_in[16];
    float* out = (float*)d_out;

    float *xgf, *xgb, *x0, *y1, *ha, *hb, *zr;
    cudaGetSymbolAddress((void**)&xgf, g_xgf);
    cudaGetSymbolAddress((void**)&xgb, g_xgb);
    cudaGetSymbolAddress((void**)&x0,  g_x0);
    cudaGetSymbolAddress((void**)&y1,  g_y1);
    cudaGetSymbolAddress((void**)&ha,  g_ha);
    cudaGetSymbolAddress((void**)&hb,  g_hb);
    cudaGetSymbolAddress((void**)&zr,  g_zr);

    // Layer 0: bidirectional over raw input (cin=24) -> x0 (128 ch)
    run_layer(x,  24,  wx_f0, b_f0, wh_f0, wx_b0, b_b0, wh_b0,
              xgf, xgb, ha, hb, zr, x0);
    // Layer 1: bidirectional over x0 (cin=128) -> y1 (128 ch)
    run_layer(x0, 128, wx_f1, b_f1, wh_f1, wx_b1, b_b1, wh_b1,
              xgf, xgb, ha, hb, zr, y1);
    // Fused head
    final_conv<<<dim3(4, NIMG), 256>>>(x0, y1, w_conv1, b_conv1, w_out, b_out, out);
}

// round 7
// speedup vs baseline: 1.3325x; 1.3325x over previous
#include <cuda_runtime.h>
#include <cuda_fp16.h>
#include <math.h>
#include <stdint.h>

// Problem constants
#define Bn 16
#define Tn 28
#define Hn 32
#define Wn 32
#define HW 1024
#define Fh 64
#define NIMG (Bn * Tn)   // 448
#define D2 32            // both directions fused: 32 "images" of hidden state

// ---------------- device scratch (no allocations allowed) ----------------
__device__ float g_xgf[(size_t)NIMG * HW * 192];  // xg forward direction
__device__ float g_xgb[(size_t)NIMG * HW * 192];  // xg backward direction
__device__ float g_x0 [(size_t)NIMG * HW * 128];  // layer-0 bidir output
__device__ float g_y1 [(size_t)NIMG * HW * 128];  // layer-1 bidir output
__device__ float g_ha [(size_t)D2 * HW * Fh];     // hidden state ping
__device__ float g_hb [(size_t)D2 * HW * Fh];     // hidden state pong
__device__ float g_zr [(size_t)D2 * HW * 128];    // sigmoided z (0-63) and r (64-127)
__device__ __half g_wt[(size_t)18 * 192 * 64];    // fp16 pre-swizzled layer-1 weights

// ---------------- packed f32x2 helpers (FFMA2 path) ----------------
__device__ __forceinline__ unsigned long long pack2(float v) {
    unsigned long long r;
    asm("mov.b64 %0, {%1, %1};" : "=l"(r) : "f"(v));
    return r;
}
__device__ __forceinline__ void ffma2(unsigned long long& d, unsigned long long a,
                                      unsigned long long b) {
    asm("fma.rn.f32x2 %0, %1, %2, %0;" : "+l"(d) : "l"(a), "l"(b));
}
__device__ __forceinline__ void unpack2(unsigned long long a, float& lo, float& hi) {
    asm("mov.b64 {%0, %1}, %2;" : "=f"(lo), "=f"(hi) : "l"(a));
}

__device__ __forceinline__ uint32_t smem_u32(const void* p) {
    uint32_t a;
    asm("{ .reg .u64 t; cvta.to.shared.u64 t, %1; cvt.u32.u64 %0, t; }"
        : "=r"(a) : "l"(p));
    return a;
}

#define SW128(b) ((b) ^ (((b) >> 3) & 0x70))

// ---------------- mma.sync helpers (legacy tensor path, sm_103-safe) --------
__device__ __forceinline__ void ldsm_x4(uint32_t& r0, uint32_t& r1,
                                        uint32_t& r2, uint32_t& r3, uint32_t addr) {
    asm volatile("ldmatrix.sync.aligned.m8n8.x4.shared.b16 {%0,%1,%2,%3}, [%4];"
                 : "=r"(r0), "=r"(r1), "=r"(r2), "=r"(r3) : "r"(addr));
}
__device__ __forceinline__ void mma16816(float* c, uint32_t a0, uint32_t a1,
                                         uint32_t a2, uint32_t a3,
                                         uint32_t b0, uint32_t b1) {
    asm volatile(
        "mma.sync.aligned.m16n8k16.row.col.f32.f16.f16.f32 "
        "{%0,%1,%2,%3}, {%4,%5,%6,%7}, {%8,%9}, {%0,%1,%2,%3};"
        : "+f"(c[0]), "+f"(c[1]), "+f"(c[2]), "+f"(c[3])
        : "r"(a0), "r"(a1), "r"(a2), "r"(a3), "r"(b0), "r"(b1));
}

// Inner accumulate (fp32 path): one cin chunk of 16, 32 couts/thread.
template<int PS>
__device__ __forceinline__ void accum16(const float* __restrict__ s_in,
                                        const float* __restrict__ s_w,
                                        int ib, unsigned long long acc[16]) {
#pragma unroll
    for (int k = 0; k < 9; k++) {
        const int off = (k / 3) * 18 + (k % 3);
#pragma unroll
        for (int ci = 0; ci < 16; ci++) {
            unsigned long long v2 = pack2(s_in[ci * PS + ib + off]);
            const float* wr = &s_w[(k * 16 + ci) * 32];
#pragma unroll
            for (int j = 0; j < 8; j++) {
                ulonglong2 wv = *(const ulonglong2*)(wr + j * 4);
                ffma2(acc[2 * j],     v2, wv.x);
                ffma2(acc[2 * j + 1], v2, wv.y);
            }
        }
    }
}

// ---------------- generic 3x3 SAME conv, NHWC fp32 (layer-0 xg) -------------
__global__ void __launch_bounds__(256)
conv3x3(const float* __restrict__ in, int cin,
        const float* __restrict__ w, int wcs, int wco,
        const float* __restrict__ bias,
        float* __restrict__ out, int ocs, int oco)
{
    __shared__ __align__(16) float s_in[16 * 325];
    __shared__ __align__(16) float s_w[9 * 16 * 32];

    const int tid = threadIdx.x;
    const int px = tid & 15, py = tid >> 4;
    const int tx0 = (blockIdx.x & 1) * 16, ty0 = (blockIdx.x >> 1) * 16;
    const int img = blockIdx.y;
    const int cg  = blockIdx.z;

    const float* inb = in + (size_t)img * HW * cin;

    unsigned long long acc[16];
#pragma unroll
    for (int i = 0; i < 16; i++) acc[i] = 0ull;

    const int nchunk = (cin + 15) >> 4;
    for (int ch = 0; ch < nchunk; ch++) {
        const int cc = ch * 16;
        __syncthreads();
        for (int idx = tid; idx < 18 * 18 * 16; idx += 256) {
            const int ci  = idx & 15;
            const int pix = idx >> 4;
            const int rx = pix % 18, ry = pix / 18;
            const int gy = ty0 + ry - 1, gx = tx0 + rx - 1;
            const int c = cc + ci;
            float v = 0.f;
            if (gy >= 0 && gy < Hn && gx >= 0 && gx < Wn && c < cin)
                v = inb[((size_t)gy * Wn + gx) * cin + c];
            s_in[ci * 325 + ry * 18 + rx] = v;
        }
        for (int idx = tid; idx < 9 * 16 * 32; idx += 256) {
            const int co = idx & 31;
            const int ci = (idx >> 5) & 15;
            const int k  = idx >> 9;
            const int c  = cc + ci;
            float v = 0.f;
            if (c < cin)
                v = w[((size_t)k * cin + c) * wcs + wco + cg * 32 + co];
            s_w[idx] = v;
        }
        __syncthreads();
        accum16<325>(s_in, s_w, py * 18 + px, acc);
    }

    float res[32];
#pragma unroll
    for (int i = 0; i < 16; i++) unpack2(acc[i], res[2 * i], res[2 * i + 1]);
    if (bias) {
#pragma unroll
        for (int i = 0; i < 32; i++) res[i] += bias[cg * 32 + i];
    }
    const size_t obase =
        ((size_t)img * HW + (size_t)(ty0 + py) * Wn + (tx0 + px)) * ocs + oco + cg * 32;
#pragma unroll
    for (int i = 0; i < 8; i++) {
        float4 v = make_float4(res[4 * i], res[4 * i + 1], res[4 * i + 2], res[4 * i + 3]);
        *(float4*)(out + obase + 4 * i) = v;
    }
}

// ---------------- layer-1 xg weight prep: transpose + fp16 + swizzle --------
// w: [3][3][128][192] fp32 -> wt: [chunk 18][n 192][64 k] fp16 with 16B-unit
// swizzle baked: logical unit g stored at g^(n&7).
__global__ void __launch_bounds__(256)
prep_w(const float* __restrict__ w, __half* __restrict__ wt)
{
    int idx = blockIdx.x * 256 + threadIdx.x;
    if (idx >= 18 * 192 * 8) return;
    const int g = idx & 7;
    const int n = (idx >> 3) % 192;
    const int c = idx / (192 * 8);
    const int tap = c >> 1;
    const int cb  = (c & 1) * 64 + g * 8;
    union { __half h[8]; uint4 u; } pk;
#pragma unroll
    for (int j = 0; j < 8; j++)
        pk.h[j] = __float2half(w[((size_t)tap * 128 + cb + j) * 192 + n]);
    const int gs = g ^ (n & 7);
    *(uint4*)&wt[(((size_t)c * 192 + n) * 8 + gs) * 8] = pk.u;
}

// ---------------- layer-1 xg conv via mma.sync (fp16 in, fp32 accum) --------
// Per CTA: M=128 px (4 image rows), N=96 couts, K=1152 in 18 chunks of 64.
// 8 warps; warp w owns m16 stripe [w*16, w*16+16), 12 n8 tiles each.
// grid (8 rowgroups, 448 imgs, 2 nhalves), 256 threads.
__global__ void __launch_bounds__(256, 2)
xg_mma(const float* __restrict__ in,       // [448][1024][128]
       const __half* __restrict__ wt,      // prepped weights
       const float* __restrict__ bias,     // [192]
       float* __restrict__ xg)             // [448][1024][192]
{
    __shared__ __align__(1024) __half sA[128 * 64];   // 16 KB
    __shared__ __align__(1024) __half sB[96 * 64];    // 12 KB

    const int tid  = threadIdx.x;
    const int lane = tid & 31;
    const int w    = tid >> 5;
    const int rg   = blockIdx.x;
    const int img  = blockIdx.y;
    const int z    = blockIdx.z;

    const float* inb = in + (size_t)img * HW * 128;
    const uint32_t A_base = smem_u32(sA);
    const uint32_t B_base = smem_u32(sB);

    // per-lane ldmatrix address components
    const int mA   = w * 16 + ((lane >> 3) & 1) * 8 + (lane & 7);
    const uint32_t a_row = A_base + mA * 128;
    const int asw  = mA & 7;
    const int ahi  = lane >> 4;                       // k-unit offset 0/1
    const int nbase = ((lane >> 4) << 3) + (lane & 7);
    const int nu   = (lane >> 3) & 1;
    const int nsw  = lane & 7;
    const uint32_t b_row = B_base + nbase * 128;

    float acc[12][4];
#pragma unroll
    for (int j = 0; j < 12; j++)
#pragma unroll
        for (int q = 0; q < 4; q++) acc[j][q] = 0.f;

    // A-build geometry for threads 0..127 (pixel = tid)
    const int ry = (tid & 127) >> 5, rx = tid & 31;

    for (int c = 0; c < 18; c++) {
        __syncthreads();
        if (tid < 128) {
            // build A: pixel tid's 64 K-elems of chunk c (fp32 -> fp16, swizzled)
            const int tap = c >> 1;
            const int cb0 = (c & 1) * 64;
            const int gy = rg * 4 + ry + (tap / 3) - 1;
            const int gx = rx + (tap % 3) - 1;
            const bool vpix = (gy >= 0 && gy < Hn && gx >= 0 && gx < Wn);
            const float* src = inb + ((size_t)gy * Wn + gx) * 128 + cb0;
            const int m = tid;
#pragma unroll
            for (int g = 0; g < 8; g++) {
                float4 v0, v1;
                if (vpix) {
                    v0 = *(const float4*)(src + g * 8);
                    v1 = *(const float4*)(src + g * 8 + 4);
                } else {
                    v0 = make_float4(0.f, 0.f, 0.f, 0.f);
                    v1 = v0;
                }
                union { __half2 h[4]; uint4 u; } pk;
                pk.h[0] = __floats2half2_rn(v0.x, v0.y);
                pk.h[1] = __floats2half2_rn(v0.z, v0.w);
                pk.h[2] = __floats2half2_rn(v1.x, v1.y);
                pk.h[3] = __floats2half2_rn(v1.z, v1.w);
                *(uint4*)((char*)sA + SW128(m * 128 + g * 16)) = pk.u;
            }
        } else {
            // copy B: 12 KB of pre-swizzled weights (linear copy)
            const uint4* wsrc = (const uint4*)(wt + (((size_t)c * 192) + z * 96) * 64);
            uint4* wdst = (uint4*)sB;
            const int t = tid - 128;
#pragma unroll
            for (int i = 0; i < 6; i++)
                wdst[t + i * 128] = wsrc[t + i * 128];
        }
        __syncthreads();

#pragma unroll
        for (int ks = 0; ks < 4; ks++) {
            uint32_t a0, a1, a2, a3;
            ldsm_x4(a0, a1, a2, a3, a_row + (((ks * 2 + ahi) ^ asw) << 4));
            const uint32_t bk = ((ks * 2 + nu) ^ nsw) << 4;
#pragma unroll
            for (int p = 0; p < 6; p++) {
                uint32_t b0, b1, b2, b3;
                ldsm_x4(b0, b1, b2, b3, b_row + p * 2048 + bk);
                mma16816(acc[2 * p],     a0, a1, a2, a3, b0, b1);
                mma16816(acc[2 * p + 1], a0, a1, a2, a3, b2, b3);
            }
        }
    }

    // ---- epilogue: registers + bias -> xg ----
    const int mlo = w * 16 + (lane >> 2);
    const int mhi = mlo + 8;
    const int gylo = rg * 4 + (mlo >> 5), gxlo = mlo & 31;
    const int gyhi = rg * 4 + (mhi >> 5), gxhi = mhi & 31;
    float* plo = xg + ((size_t)img * HW + (size_t)gylo * Wn + gxlo) * 192 + z * 96;
    float* phi = xg + ((size_t)img * HW + (size_t)gyhi * Wn + gxhi) * 192 + z * 96;
    const int nc = (lane & 3) * 2;
#pragma unroll
    for (int j = 0; j < 12; j++) {
        const float2 bz = *(const float2*)&bias[z * 96 + j * 8 + nc];
        float2 vlo = make_float2(acc[j][0] + bz.x, acc[j][1] + bz.y);
        float2 vhi = make_float2(acc[j][2] + bz.x, acc[j][3] + bz.y);
        *(float2*)&plo[j * 8 + nc] = vlo;
        *(float2*)&phi[j * 8 + nc] = vhi;
    }
}

// ---------------- scan step kernel 1: zr = sigmoid(xg + conv(h, wh_zr)) -----
__global__ void __launch_bounds__(128)
gru_k1(const float* __restrict__ h,
       const float* __restrict__ whf, const float* __restrict__ whb,
       const float* __restrict__ xgf, const float* __restrict__ xgb,
       float* __restrict__ zr, int s)
{
    __shared__ __align__(16) float s_in[16 * 181];
    __shared__ __align__(16) float s_w[9 * 16 * 32];

    const int tid = threadIdx.x;
    const int px = tid & 15, py = tid >> 4;
    const int tx0 = (blockIdx.x & 1) * 16, ty0 = (blockIdx.x >> 1) * 8;
    const int img = blockIdx.y;
    const int cg  = blockIdx.z;
    const int dir = img >> 4;

    const float* hb = h + (size_t)img * HW * Fh;
    const float* wh = dir ? whb : whf;

    unsigned long long acc[16];
#pragma unroll
    for (int i = 0; i < 16; i++) acc[i] = 0ull;

    for (int ch = 0; ch < 4; ch++) {
        const int cc = ch * 16;
        __syncthreads();
        for (int idx = tid; idx < 10 * 18 * 16; idx += 128) {
            const int ci  = idx & 15;
            const int pix = idx >> 4;
            const int rx = pix % 18, ry = pix / 18;
            const int gy = ty0 + ry - 1, gx = tx0 + rx - 1;
            float v = 0.f;
            if (gy >= 0 && gy < Hn && gx >= 0 && gx < Wn)
                v = hb[((size_t)gy * Wn + gx) * Fh + cc + ci];
            s_in[ci * 181 + ry * 18 + rx] = v;
        }
        for (int idx = tid; idx < 9 * 16 * 32; idx += 128) {
            const int co = idx & 31;
            const int ci = (idx >> 5) & 15;
            const int k  = idx >> 9;
            s_w[idx] = wh[((size_t)k * Fh + cc + ci) * 192 + cg * 32 + co];
        }
        __syncthreads();
        accum16<181>(s_in, s_w, py * 18 + px, acc);
    }

    float res[32];
#pragma unroll
    for (int i = 0; i < 16; i++) unpack2(acc[i], res[2 * i], res[2 * i + 1]);

    const int b = img & 15;
    const int t = dir ? (Tn - 1 - s) : s;
    const int gpx = (ty0 + py) * Wn + tx0 + px;
    const float* xp = (dir ? xgb : xgf) + ((size_t)(b * Tn + t) * HW + gpx) * 192 + cg * 32;
    float* zp = zr + ((size_t)img * HW + gpx) * 128 + cg * 32;
#pragma unroll
    for (int i = 0; i < 32; i++) {
        zp[i] = 1.f / (1.f + expf(-(xp[i] + res[i])));
    }
}

// ---------------- scan step kernel 2: full GRU update -----------------------
__global__ void __launch_bounds__(128)
gru_k2(const float* __restrict__ h,
       const float* __restrict__ whf, const float* __restrict__ whb,
       const float* __restrict__ xgf, const float* __restrict__ xgb,
       const float* __restrict__ zr, float* __restrict__ hn,
       float* __restrict__ y, int s)
{
    __shared__ __align__(16) float s_in[16 * 181];
    __shared__ __align__(16) float s_w[9 * 16 * 32];

    const int tid = threadIdx.x;
    const int px = tid & 15, py = tid >> 4;
    const int tx0 = (blockIdx.x & 1) * 16, ty0 = (blockIdx.x >> 1) * 8;
    const int img = blockIdx.y;
    const int cg  = blockIdx.z;
    const int dir = img >> 4;

    const float* hbase  = h  + (size_t)img * HW * Fh;
    const float* zrbase = zr + (size_t)img * HW * 128;
    const float* wh = dir ? whb : whf;

    unsigned long long acc[16];
#pragma unroll
    for (int i = 0; i < 16; i++) acc[i] = 0ull;

    for (int ch = 0; ch < 4; ch++) {
        const int cc = ch * 16;
        __syncthreads();
        for (int idx = tid; idx < 10 * 18 * 16; idx += 128) {
            const int ci  = idx & 15;
            const int pix = idx >> 4;
            const int rx = pix % 18, ry = pix / 18;
            const int gy = ty0 + ry - 1, gx = tx0 + rx - 1;
            float v = 0.f;
            if (gy >= 0 && gy < Hn && gx >= 0 && gx < Wn) {
                const size_t p = (size_t)gy * Wn + gx;
                v = zrbase[p * 128 + 64 + cc + ci] * hbase[p * Fh + cc + ci];
            }
            s_in[ci * 181 + ry * 18 + rx] = v;
        }
        for (int idx = tid; idx < 9 * 16 * 32; idx += 128) {
            const int co = idx & 31;
            const int ci = (idx >> 5) & 15;
            const int k  = idx >> 9;
            s_w[idx] = wh[((size_t)k * Fh + cc + ci) * 192 + 128 + cg * 32 + co];
        }
        __syncthreads();
        accum16<181>(s_in, s_w, py * 18 + px, acc);
    }

    float res[32];
#pragma unroll
    for (int i = 0; i < 16; i++) unpack2(acc[i], res[2 * i], res[2 * i + 1]);

    const int b = img & 15;
    const int t = dir ? (Tn - 1 - s) : s;
    const int gpx = (ty0 + py) * Wn + tx0 + px;
    const int c0 = cg * 32;
    const size_t frame = (size_t)(b * Tn + t) * HW + gpx;
    const float* xp = (dir ? xgb : xgf) + frame * 192 + 128 + c0;
    const float* zp = zrbase + (size_t)gpx * 128 + c0;
    const float* hp = hbase + (size_t)gpx * Fh + c0;
    float* hnp = hn + ((size_t)img * HW + gpx) * Fh + c0;
    float* yp  = y + frame * 128 + dir * 64 + c0;
#pragma unroll
    for (int i = 0; i < 32; i++) {
        const float hh = tanhf(xp[i] + res[i]);
        const float zz = zp[i];
        const float v  = zz * hp[i] + (1.f - zz) * hh;
        hnp[i] = v;
        yp[i]  = v;
    }
}

// ---------------- fused head: 3x3 conv (256->32) + 1x1 (32->1) + ReLU -------
__global__ void __launch_bounds__(256)
final_conv(const float* __restrict__ x0, const float* __restrict__ y1,
           const float* __restrict__ wc, const float* __restrict__ bc,
           const float* __restrict__ wo, const float* __restrict__ bo,
           float* __restrict__ out)
{
    __shared__ __align__(16) float s_in[16 * 325];
    __shared__ __align__(16) float s_w[9 * 16 * 32];

    const int tid = threadIdx.x;
    const int px = tid & 15, py = tid >> 4;
    const int tx0 = (blockIdx.x & 1) * 16, ty0 = (blockIdx.x >> 1) * 16;
    const int img = blockIdx.y;

    const float* x0b = x0 + (size_t)img * HW * 128;
    const float* y1b = y1 + (size_t)img * HW * 128;

    unsigned long long acc[16];
#pragma unroll
    for (int i = 0; i < 16; i++) acc[i] = 0ull;

    for (int ch = 0; ch < 16; ch++) {
        const int cc = ch * 16;
        __syncthreads();
        for (int idx = tid; idx < 18 * 18 * 16; idx += 256) {
            const int ci  = idx & 15;
            const int pix = idx >> 4;
            const int rx = pix % 18, ry = pix / 18;
            const int gy = ty0 + ry - 1, gx = tx0 + rx - 1;
            float v = 0.f;
            if (gy >= 0 && gy < Hn && gx >= 0 && gx < Wn) {
                const int c = cc + ci;
                const size_t pbase = ((size_t)gy * Wn + gx) * 128;
                v = (c < 128) ? (x0b[pbase + c] + y1b[pbase + c]) : x0b[pbase + c - 128];
            }
            s_in[ci * 325 + ry * 18 + rx] = v;
        }
        for (int idx = tid; idx < 9 * 16 * 32; idx += 256) {
            const int co = idx & 31;
            const int ci = (idx >> 5) & 15;
            const int k  = idx >> 9;
            s_w[idx] = wc[((size_t)k * 256 + cc + ci) * 32 + co];
        }
        __syncthreads();
        accum16<325>(s_in, s_w, py * 18 + px, acc);
    }

    float res[32];
#pragma unroll
    for (int i = 0; i < 16; i++) unpack2(acc[i], res[2 * i], res[2 * i + 1]);

    float o = bo[0];
#pragma unroll
    for (int i = 0; i < 32; i++) o += (res[i] + bc[i]) * wo[i];
    o = fmaxf(o, 0.f);
    out[(size_t)img * HW + (size_t)(ty0 + py) * Wn + (tx0 + px)] = o;
}

// ---------------- host orchestration ----------------
static void run_scan(const float* whf, const float* whb,
                     const float* xgf, const float* xgb,
                     float* ha, float* hbuf, float* zr, float* yout)
{
    cudaMemsetAsync(ha, 0, (size_t)D2 * HW * Fh * sizeof(float));
    float* hc = ha;
    float* hx = hbuf;
    for (int s = 0; s < Tn; s++) {
        gru_k1<<<dim3(8, D2, 4), 128>>>(hc, whf, whb, xgf, xgb, zr, s);
        gru_k2<<<dim3(8, D2, 2), 128>>>(hc, whf, whb, xgf, xgb, zr, hx, yout, s);
        float* tmp = hc; hc = hx; hx = tmp;
    }
}

extern "C" void kernel_launch(void* const* d_in, const int* in_sizes, int n_in,
                              void* d_out, int out_size)
{
    (void)in_sizes; (void)n_in; (void)out_size;
    const float* x       = (const float*)d_in[0];
    const float* wx_f0   = (const float*)d_in[1];
    const float* wh_f0   = (const float*)d_in[2];
    const float* b_f0    = (const float*)d_in[3];
    const float* wx_b0   = (const float*)d_in[4];
    const float* wh_b0   = (const float*)d_in[5];
    const float* b_b0    = (const float*)d_in[6];
    const float* wx_f1   = (const float*)d_in[7];
    const float* wh_f1   = (const float*)d_in[8];
    const float* b_f1    = (const float*)d_in[9];
    const float* wx_b1   = (const float*)d_in[10];
    const float* wh_b1   = (const float*)d_in[11];
    const float* b_b1    = (const float*)d_in[12];
    const float* w_conv1 = (const float*)d_in[13];
    const float* b_conv1 = (const float*)d_in[14];
    const float* w_out   = (const float*)d_in[15];
    const float* b_out   = (const float*)d_in[16];
    float* out = (float*)d_out;

    float *xgf, *xgb, *x0, *y1, *ha, *hb, *zr;
    __half* wt;
    cudaGetSymbolAddress((void**)&xgf, g_xgf);
    cudaGetSymbolAddress((void**)&xgb, g_xgb);
    cudaGetSymbolAddress((void**)&x0,  g_x0);
    cudaGetSymbolAddress((void**)&y1,  g_y1);
    cudaGetSymbolAddress((void**)&ha,  g_ha);
    cudaGetSymbolAddress((void**)&hb,  g_hb);
    cudaGetSymbolAddress((void**)&zr,  g_zr);
    cudaGetSymbolAddress((void**)&wt,  g_wt);

    // ---- Layer 0 (cin=24, fp32 conv for xg) ----
    conv3x3<<<dim3(4, NIMG, 6), 256>>>(x, 24, wx_f0, 192, 0, b_f0, xgf, 192, 0);
    conv3x3<<<dim3(4, NIMG, 6), 256>>>(x, 24, wx_b0, 192, 0, b_b0, xgb, 192, 0);
    run_scan(wh_f0, wh_b0, xgf, xgb, ha, hb, zr, x0);

    // ---- Layer 1 (cin=128, mma.sync fp16 xg convs) ----
    prep_w<<<108, 256>>>(wx_f1, wt);
    xg_mma<<<dim3(8, NIMG, 2), 256>>>(x0, wt, b_f1, xgf);
    prep_w<<<108, 256>>>(wx_b1, wt);
    xg_mma<<<dim3(8, NIMG, 2), 256>>>(x0, wt, b_b1, xgb);
    run_scan(wh_f1, wh_b1, xgf, xgb, ha, hb, zr, y1);

    // ---- Fused head ----
    final_conv<<<dim3(4, NIMG), 256>>>(x0, y1, w_conv1, b_conv1, w_out, b_out, out);
}